// round 12
// baseline (speedup 1.0000x reference)
#include <cuda_runtime.h>
#include <cuda_bf16.h>
#include <math_constants.h>

#define N_TOK  16384
#define DIMK   256
#define NCTA   148
#define NUNITS 1024            // 128 rowblocks x 8 column chunks (16 tiles each)
#define RSTRIDE 528u
#define TILE_B (128u * RSTRIDE)
#define SMEM_DYN (3u * TILE_B)

__device__ float2 g_cp[256 * N_TOK];       // per (rowblock, warp-half, col) partial
__device__ float2 g_rpu[NUNITS * 128];     // per (unit, local row) partial (run-final or neutral)
__device__ float  g_diag[N_TOK];
__device__ float  g_rowloss[2 * N_TOK];

__device__ __forceinline__ unsigned smem_u32(const void* p) {
    unsigned a;
    asm("{ .reg .u64 t; cvta.to.shared.u64 t, %1; cvt.u32.u64 %0, t; }" : "=r"(a) : "l"(p));
    return a;
}
__device__ __forceinline__ unsigned bf16x2_pack(float lo, float hi) {
    unsigned r;
    asm("cvt.rn.bf16x2.f32 %0, %1, %2;" : "=r"(r) : "f"(hi), "f"(lo));
    return r;
}
__device__ __forceinline__ float ex2f(float x) {
    float y; asm("ex2.approx.ftz.f32 %0, %1;" : "=f"(y) : "f"(x)); return y;
}
__device__ __forceinline__ float expsum8_m(const float* v, float k2, float base) {
    float s0 = 0.f, s1 = 0.f;
#pragma unroll
    for (int i = 0; i < 8; i += 2) {
        s0 += ex2f(fmaf(v[i],     k2, -base));
        s1 += ex2f(fmaf(v[i + 1], k2, -base));
    }
    return s0 + s1;
}

#define MBARRIER_INIT(a, c) \
    asm volatile("mbarrier.init.shared.b64 [%0], %1;" :: "r"((unsigned)(a)), "r"((unsigned)(c)) : "memory")
#define MBARRIER_ARRIVE(a) \
    asm volatile("mbarrier.arrive.shared.b64 _, [%0];" :: "r"((unsigned)(a)) : "memory")
#define MBARRIER_WAIT(a, par) do { \
    unsigned _m = (unsigned)(a), _p = (unsigned)(par), _d; \
    asm volatile("{ .reg .pred p; mbarrier.try_wait.parity.acquire.cta.shared::cta.b64 p, [%1], %2; selp.b32 %0,1,0,p; }" \
        : "=r"(_d) : "r"(_m), "r"(_p) : "memory"); \
    if (!_d) asm volatile("{ .reg .pred P; WL_%=: mbarrier.try_wait.parity.acquire.cta.shared::cta.b64 P, [%0], %1, 0x989680; @P bra.uni WD_%=; bra.uni WL_%=; WD_%=: }" \
        :: "r"(_m), "r"(_p) : "memory"); \
} while (0)

#define STS128(r0, r1, r2, r3, a) \
    asm volatile("st.shared.v4.b32 [%0], {%1,%2,%3,%4};" :: "r"((unsigned)(a)), "r"(r0), "r"(r1), "r"(r2), "r"(r3) : "memory")
#define BAR_SYNC(id, n) asm volatile("bar.sync %0, %1;" :: "r"(id), "r"(n) : "memory")

#define LDSM_X4(d, a) \
    asm volatile("ldmatrix.sync.aligned.m8n8.x4.shared.b16 {%0,%1,%2,%3}, [%4];" \
        : "=r"((d)[0]), "=r"((d)[1]), "=r"((d)[2]), "=r"((d)[3]) : "r"((unsigned)(a)))
#define LDSM_X4T(d, a) \
    asm volatile("ldmatrix.sync.aligned.m8n8.x4.trans.shared.b16 {%0,%1,%2,%3}, [%4];" \
        : "=r"((d)[0]), "=r"((d)[1]), "=r"((d)[2]), "=r"((d)[3]) : "r"((unsigned)(a)))

#define MMA16816(d, a, b0, b1) \
    asm volatile("mma.sync.aligned.m16n8k16.row.col.f32.bf16.bf16.f32 " \
        "{%0,%1,%2,%3}, {%4,%5,%6,%7}, {%8,%9}, {%0,%1,%2,%3};" \
        : "+f"((d)[0]), "+f"((d)[1]), "+f"((d)[2]), "+f"((d)[3]) \
        : "r"((a)[0]), "r"((a)[1]), "r"((a)[2]), "r"((a)[3]), "r"(b0), "r"(b1))

// Fill a 128x256 tile into padded-row smem, converting fp32 -> bf16 on the fly.
__device__ __forceinline__ void fill_tile_cvt(unsigned sbase, const float4* __restrict__ src,
                                              int t0, int stride) {
#pragma unroll 4
    for (int idx = t0; idx < 4096; idx += stride) {
        const int row = idx >> 5, ch = idx & 31;
        float4 v0 = src[row * 64 + ch * 2];
        float4 v1 = src[row * 64 + ch * 2 + 1];
        unsigned r0 = bf16x2_pack(v0.x, v0.y), r1 = bf16x2_pack(v0.z, v0.w);
        unsigned r2 = bf16x2_pack(v1.x, v1.y), r3 = bf16x2_pack(v1.z, v1.w);
        STS128(r0, r1, r2, r3, sbase + (unsigned)row * RSTRIDE + (unsigned)ch * 16u);
    }
}

// Persistent: 148 CTAs, static unit ranges. Unit = (rowblock rb = u>>3, chunk = u&7).
__global__ void __launch_bounds__(512, 1)
clip_main(const float* __restrict__ img, const float* __restrict__ txt,
          const float* __restrict__ scale_ptr)
{
    extern __shared__ char dsm[];
    __shared__ __align__(8) unsigned long long sh_bar[4];
    __shared__ float sm_m[512], sm_s[512], sm_p[128];

    const int tid = threadIdx.x, wid = tid >> 5, lane = tid & 31;
    const int cta = blockIdx.x;
    const int u0 = (cta * NUNITS) / NCTA;
    const int u1 = ((cta + 1) * NUNITS) / NCTA;

    const unsigned abase = smem_u32(dsm);
    const unsigned bb[2] = { abase + TILE_B, abase + 2u * TILE_B };
    const unsigned smbar = smem_u32(sh_bar);

    if (tid == 0) {
        MBARRIER_INIT(smbar + 0, 256);  MBARRIER_INIT(smbar + 8, 256);
        MBARRIER_INIT(smbar + 16, 256); MBARRIER_INIT(smbar + 24, 256);
    }
    __syncthreads();

    const float scale = *scale_ptr;
    const float k2 = scale * 1.4426950408889634f;

    if (wid >= 8) {
        // ---------- Loaders: stream B tiles (fp32 -> bf16 cvt inline) ----------
        const int ltid = tid - 256;
        const float4* bsrc = (const float4*)txt;
        int c = 0, ph[2] = {0, 0};
        for (int u = u0; u < u1; ++u) {
            const int chunk = u & 7;
            for (int t = 0; t < 16; ++t, ++c) {
                const int b = c & 1;
                if (c >= 2) { MBARRIER_WAIT(smbar + 16 + (b << 3), ph[b]); ph[b] ^= 1; }
                fill_tile_cvt(bb[b], bsrc + (size_t)(chunk * 16 + t) * 8192, ltid, 256);
                MBARRIER_ARRIVE(smbar + (b << 3));
            }
        }
    } else {
        // ---------- Compute warps ----------
        const int wx = wid & 1, wy = wid >> 1;
        unsigned aAddr[4];
#pragma unroll
        for (int mt = 0; mt < 4; ++mt) {
            unsigned row = (unsigned)(wx * 64 + mt * 16 + (lane & 7) + ((lane >> 3) & 1) * 8);
            aAddr[mt] = abase + row * RSTRIDE + (unsigned)(lane >> 4) * 16u;
        }
        unsigned bOff[2];
#pragma unroll
        for (int nt2 = 0; nt2 < 2; ++nt2) {
            unsigned row = (unsigned)(wy * 32 + nt2 * 16 + (lane & 7) + ((lane >> 4) & 1) * 8);
            bOff[nt2] = row * RSTRIDE + (unsigned)((lane >> 3) & 1) * 16u;
        }

        float mst[8], sst[8];
#pragma unroll
        for (int i = 0; i < 8; ++i) { mst[i] = -1e30f; sst[i] = 0.0f; }

        int c = 0, ph[2] = {0, 0}, prev_rb = -1, run_u0 = u0;

        for (int u = u0; u < u1; ++u) {
            const int rb = u >> 3, chunk = u & 7;
            const int rowBase = rb << 7;
            if (rb != prev_rb) {
                if (prev_rb >= 0) {
                    // ---- finalize run [run_u0, u) of prev_rb ----
                    if ((lane & 3) == 0) {
#pragma unroll
                        for (int mt = 0; mt < 4; ++mt)
#pragma unroll
                            for (int h = 0; h < 2; ++h) {
                                const int row = wx * 64 + mt * 16 + (lane >> 2) + 8 * h;
                                sm_m[wy * 128 + row] = mst[mt * 2 + h];
                                sm_s[wy * 128 + row] = sst[mt * 2 + h];
                            }
                    }
                    BAR_SYNC(1, 256);
                    if (tid < 128) {
                        float mM = sm_m[tid];
#pragma unroll
                        for (int q = 1; q < 4; ++q) mM = fmaxf(mM, sm_m[q * 128 + tid]);
                        float sM = 0.0f;
#pragma unroll
                        for (int q = 0; q < 4; ++q)
                            sM += sm_s[q * 128 + tid] * ex2f(k2 * (sm_m[q * 128 + tid] - mM));
                        g_rpu[(size_t)(u - 1) * 128 + tid] = make_float2(mM, sM);
                        const float2 neutral = make_float2(-1e30f, 0.0f);
                        for (int uu = run_u0; uu < u - 1; ++uu)
                            g_rpu[(size_t)uu * 128 + tid] = neutral;
                        const int dchunk = prev_rb >> 4;
                        const int clo = run_u0 - (prev_rb << 3), chi = u - (prev_rb << 3);
                        if (dchunk >= clo && dchunk < chi)
                            g_diag[(prev_rb << 7) + tid] = sm_p[tid];
                    }
                    BAR_SYNC(1, 256);
#pragma unroll
                    for (int i = 0; i < 8; ++i) { mst[i] = -1e30f; sst[i] = 0.0f; }
                    run_u0 = u;
                }
                fill_tile_cvt(abase, (const float4*)img + (size_t)rowBase * 64, tid, 256);
                BAR_SYNC(1, 256);
                prev_rb = rb;
            }

            for (int t = 0; t < 16; ++t, ++c) {
                const int b = c & 1;
                const int jj = chunk * 16 + t;
                MBARRIER_WAIT(smbar + (b << 3), ph[b]); ph[b] ^= 1;
                const unsigned bbase = bb[b];

                float acc[4][4][4];
#pragma unroll
                for (int mt = 0; mt < 4; ++mt)
#pragma unroll
                    for (int nt = 0; nt < 4; ++nt)
#pragma unroll
                        for (int e = 0; e < 4; ++e) acc[mt][nt][e] = 0.0f;

#pragma unroll 4
                for (int ks = 0; ks < 16; ++ks) {
                    const unsigned ko = (unsigned)ks * 32u;
                    unsigned a[4][4];
#pragma unroll
                    for (int mt = 0; mt < 4; ++mt) LDSM_X4(a[mt], aAddr[mt] + ko);
#pragma unroll
                    for (int nt2 = 0; nt2 < 2; ++nt2) {
                        unsigned bf[4];
                        LDSM_X4T(bf, bbase + bOff[nt2] + ko);
#pragma unroll
                        for (int mt = 0; mt < 4; ++mt) {
                            MMA16816(acc[mt][nt2 * 2 + 0], a[mt], bf[0], bf[1]);
                            MMA16816(acc[mt][nt2 * 2 + 1], a[mt], bf[2], bf[3]);
                        }
                    }
                }
                MBARRIER_ARRIVE(smbar + 16 + (b << 3));

                // Row-direction online LSE (warp-uniform skip; stats carried across units)
#pragma unroll
                for (int mt = 0; mt < 4; ++mt)
#pragma unroll
                    for (int h = 0; h < 2; ++h) {
                        const int st = mt * 2 + h;
                        float v[8];
#pragma unroll
                        for (int nt = 0; nt < 4; ++nt) {
                            v[nt * 2 + 0] = acc[mt][nt][h * 2 + 0];
                            v[nt * 2 + 1] = acc[mt][nt][h * 2 + 1];
                        }
                        if (jj == rb) {
                            const int row = wx * 64 + mt * 16 + (lane >> 2) + 8 * h;
#pragma unroll
                            for (int nt = 0; nt < 4; ++nt)
#pragma unroll
                                for (int e = 0; e < 2; ++e) {
                                    const int col = wy * 32 + nt * 8 + 2 * (lane & 3) + e;
                                    if (col == row) sm_p[row] = v[nt * 2 + e];
                                }
                        }
                        float vm = v[0];
#pragma unroll
                        for (int i = 1; i < 8; ++i) vm = fmaxf(vm, v[i]);
                        vm = fmaxf(vm, __shfl_xor_sync(0xffffffffu, vm, 1));
                        vm = fmaxf(vm, __shfl_xor_sync(0xffffffffu, vm, 2));
                        if (__all_sync(0xffffffffu, vm < mst[st] - 2.0f)) continue;
                        const float mnew = fmaxf(mst[st], vm);
                        const float base = k2 * mnew;
                        float sum = expsum8_m(v, k2, base);
                        sum += __shfl_xor_sync(0xffffffffu, sum, 1);
                        sum += __shfl_xor_sync(0xffffffffu, sum, 2);
                        sst[st] = fmaf(sst[st], ex2f(fmaf(mst[st], k2, -base)), sum);
                        mst[st] = mnew;
                    }

                // Column partial over this warp's 64 rows
                {
                    float cm[8], cs[8];
#pragma unroll
                    for (int nt = 0; nt < 4; ++nt)
#pragma unroll
                        for (int e = 0; e < 2; ++e) {
                            const int ci = nt * 2 + e;
                            float v0 = fmaxf(fmaxf(acc[0][nt][e], acc[0][nt][2 + e]),
                                             fmaxf(acc[1][nt][e], acc[1][nt][2 + e]));
                            float v1 = fmaxf(fmaxf(acc[2][nt][e], acc[2][nt][2 + e]),
                                             fmaxf(acc[3][nt][e], acc[3][nt][2 + e]));
                            cm[ci] = fmaxf(v0, v1);
                        }
#pragma unroll
                    for (int ci = 0; ci < 8; ++ci) {
                        cm[ci] = fmaxf(cm[ci], __shfl_xor_sync(0xffffffffu, cm[ci], 4));
                        cm[ci] = fmaxf(cm[ci], __shfl_xor_sync(0xffffffffu, cm[ci], 8));
                        cm[ci] = fmaxf(cm[ci], __shfl_xor_sync(0xffffffffu, cm[ci], 16));
                    }
#pragma unroll
                    for (int nt = 0; nt < 4; ++nt)
#pragma unroll
                        for (int e = 0; e < 2; ++e) {
                            const int ci = nt * 2 + e;
                            float v[8];
#pragma unroll
                            for (int mt = 0; mt < 4; ++mt) {
                                v[mt * 2 + 0] = acc[mt][nt][e];
                                v[mt * 2 + 1] = acc[mt][nt][2 + e];
                            }
                            cs[ci] = expsum8_m(v, k2, k2 * cm[ci]);
                        }
#pragma unroll
                    for (int ci = 0; ci < 8; ++ci) {
                        cs[ci] += __shfl_xor_sync(0xffffffffu, cs[ci], 4);
                        cs[ci] += __shfl_xor_sync(0xffffffffu, cs[ci], 8);
                        cs[ci] += __shfl_xor_sync(0xffffffffu, cs[ci], 16);
                    }
                    if (lane < 4) {
#pragma unroll
                        for (int nt = 0; nt < 4; ++nt)
#pragma unroll
                            for (int e = 0; e < 2; ++e) {
                                const int ci = nt * 2 + e;
                                const int cg = jj * 128 + wy * 32 + nt * 8 + 2 * lane + e;
                                g_cp[(size_t)(rb * 2 + wx) * N_TOK + cg] = make_float2(cm[ci], cs[ci]);
                            }
                    }
                }
            }
        }

        // ---- finalize last run [run_u0, u1) ----
        if ((lane & 3) == 0) {
#pragma unroll
            for (int mt = 0; mt < 4; ++mt)
#pragma unroll
                for (int h = 0; h < 2; ++h) {
                    const int row = wx * 64 + mt * 16 + (lane >> 2) + 8 * h;
                    sm_m[wy * 128 + row] = mst[mt * 2 + h];
                    sm_s[wy * 128 + row] = sst[mt * 2 + h];
                }
        }
        BAR_SYNC(1, 256);
        if (tid < 128) {
            float mM = sm_m[tid];
#pragma unroll
            for (int q = 1; q < 4; ++q) mM = fmaxf(mM, sm_m[q * 128 + tid]);
            float sM = 0.0f;
#pragma unroll
            for (int q = 0; q < 4; ++q)
                sM += sm_s[q * 128 + tid] * ex2f(k2 * (sm_m[q * 128 + tid] - mM));
            g_rpu[(size_t)(u1 - 1) * 128 + tid] = make_float2(mM, sM);
            const float2 neutral = make_float2(-1e30f, 0.0f);
            for (int uu = run_u0; uu < u1 - 1; ++uu)
                g_rpu[(size_t)uu * 128 + tid] = neutral;
            const int dchunk = prev_rb >> 4;
            const int clo = run_u0 - (prev_rb << 3), chi = u1 - (prev_rb << 3);
            if (dchunk >= clo && dchunk < chi)
                g_diag[(prev_rb << 7) + tid] = sm_p[tid];
        }
        BAR_SYNC(1, 256);
    }
}

__global__ void __launch_bounds__(256) clip_colred(const float* __restrict__ scale_ptr)
{
    const float scale = *scale_ptr;
    const float k2 = scale * 1.4426950408889634f;
    const int c = blockIdx.x * 256 + threadIdx.x;

    float M = -CUDART_INF_F;
#pragma unroll 4
    for (int i = 0; i < 256; ++i) M = fmaxf(M, g_cp[(size_t)i * N_TOK + c].x);
    float S = 0.0f;
#pragma unroll 4
    for (int i = 0; i < 256; ++i) {
        float2 p = g_cp[(size_t)i * N_TOK + c];
        S += p.y * ex2f(k2 * (p.x - M));
    }
    const float d = scale * g_diag[c];
    g_rowloss[N_TOK + c] = 0.69314718055994531f * fmaf(k2, M, __log2f(S)) - d;

    const int rb = c >> 7, lr = c & 127;
    float mM = -CUDART_INF_F;
#pragma unroll
    for (int k = 0; k < 8; ++k) mM = fmaxf(mM, g_rpu[(size_t)(rb * 8 + k) * 128 + lr].x);
    float sM = 0.0f;
#pragma unroll
    for (int k = 0; k < 8; ++k) {
        float2 p = g_rpu[(size_t)(rb * 8 + k) * 128 + lr];
        sM += p.y * ex2f(k2 * (p.x - mM));
    }
    g_rowloss[c] = 0.69314718055994531f * fmaf(k2, mM, __log2f(sM)) - d;
}

__global__ void __launch_bounds__(1024) clip_reduce(float* __restrict__ out)
{
    __shared__ float sm[1024];
    float a = 0.0f;
    const float4* p = (const float4*)g_rowloss;
#pragma unroll 4
    for (int i = threadIdx.x; i < 8192; i += 1024) {
        float4 v = p[i];
        a += (v.x + v.y) + (v.z + v.w);
    }
    sm[threadIdx.x] = a;
    __syncthreads();
    for (int st = 512; st > 0; st >>= 1) {
        if (threadIdx.x < st) sm[threadIdx.x] += sm[threadIdx.x + st];
        __syncthreads();
    }
    if (threadIdx.x == 0) out[0] = sm[0] * (1.0f / 32768.0f);
}

extern "C" void kernel_launch(void* const* d_in, const int* in_sizes, int n_in,
                              void* d_out, int out_size)
{
    (void)in_sizes; (void)n_in; (void)out_size;
    const float* img = (const float*)d_in[0];
    const float* txt = (const float*)d_in[1];
    const float* scl = (const float*)d_in[2];

    cudaFuncSetAttribute(clip_main, cudaFuncAttributeMaxDynamicSharedMemorySize, SMEM_DYN);
    clip_main<<<NCTA, 512, SMEM_DYN>>>(img, txt, scl);
    clip_colred<<<64, 256>>>(scl);
    clip_reduce<<<1, 1024>>>((float*)d_out);
}

// round 13
// speedup vs baseline: 1.0946x; 1.0946x over previous
#include <cuda_runtime.h>
#include <cuda_bf16.h>
#include <math_constants.h>

#define N_TOK  16384
#define DIMK   256
#define NCTA   148
#define NUNITS 1024            // 128 rowblocks x 8 column chunks (16 tiles each)
#define RSTRIDE 528u
#define TILE_B (128u * RSTRIDE)
#define SMEM_DYN (3u * TILE_B)

__device__ __align__(16) __nv_bfloat16 g_bf[2][N_TOK * DIMK];
__device__ float2 g_cp[256 * N_TOK];       // per (rowblock, warp-half, col) partial
__device__ float2 g_rpu[NUNITS * 128];     // per (unit, local row) partial (run-final or neutral)
__device__ float  g_diag[N_TOK];
__device__ float  g_rowloss[2 * N_TOK];

__device__ __forceinline__ unsigned smem_u32(const void* p) {
    unsigned a;
    asm("{ .reg .u64 t; cvta.to.shared.u64 t, %1; cvt.u32.u64 %0, t; }" : "=r"(a) : "l"(p));
    return a;
}
__device__ __forceinline__ unsigned bf16x2_pack(float lo, float hi) {
    unsigned r;
    asm("cvt.rn.bf16x2.f32 %0, %1, %2;" : "=r"(r) : "f"(hi), "f"(lo));
    return r;
}
__device__ __forceinline__ float ex2f(float x) {
    float y; asm("ex2.approx.ftz.f32 %0, %1;" : "=f"(y) : "f"(x)); return y;
}
__device__ __forceinline__ float expsum8_m(const float* v, float k2, float base) {
    float s0 = 0.f, s1 = 0.f;
#pragma unroll
    for (int i = 0; i < 8; i += 2) {
        s0 += ex2f(fmaf(v[i],     k2, -base));
        s1 += ex2f(fmaf(v[i + 1], k2, -base));
    }
    return s0 + s1;
}

#define MBARRIER_INIT(a, c) \
    asm volatile("mbarrier.init.shared.b64 [%0], %1;" :: "r"((unsigned)(a)), "r"((unsigned)(c)) : "memory")
#define MBARRIER_ARRIVE(a) \
    asm volatile("mbarrier.arrive.shared.b64 _, [%0];" :: "r"((unsigned)(a)) : "memory")
#define MBARRIER_WAIT(a, par) do { \
    unsigned _m = (unsigned)(a), _p = (unsigned)(par), _d; \
    asm volatile("{ .reg .pred p; mbarrier.try_wait.parity.acquire.cta.shared::cta.b64 p, [%1], %2; selp.b32 %0,1,0,p; }" \
        : "=r"(_d) : "r"(_m), "r"(_p) : "memory"); \
    if (!_d) asm volatile("{ .reg .pred P; WL_%=: mbarrier.try_wait.parity.acquire.cta.shared::cta.b64 P, [%0], %1, 0x989680; @P bra.uni WD_%=; bra.uni WL_%=; WD_%=: }" \
        :: "r"(_m), "r"(_p) : "memory"); \
} while (0)

#define STS128(r0, r1, r2, r3, a) \
    asm volatile("st.shared.v4.b32 [%0], {%1,%2,%3,%4};" :: "r"((unsigned)(a)), "r"(r0), "r"(r1), "r"(r2), "r"(r3) : "memory")
#define BAR_SYNC(id, n) asm volatile("bar.sync %0, %1;" :: "r"(id), "r"(n) : "memory")

#define LDSM_X4(d, a) \
    asm volatile("ldmatrix.sync.aligned.m8n8.x4.shared.b16 {%0,%1,%2,%3}, [%4];" \
        : "=r"((d)[0]), "=r"((d)[1]), "=r"((d)[2]), "=r"((d)[3]) : "r"((unsigned)(a)))
#define LDSM_X4T(d, a) \
    asm volatile("ldmatrix.sync.aligned.m8n8.x4.trans.shared.b16 {%0,%1,%2,%3}, [%4];" \
        : "=r"((d)[0]), "=r"((d)[1]), "=r"((d)[2]), "=r"((d)[3]) : "r"((unsigned)(a)))

#define MMA16816(d, a, b0, b1) \
    asm volatile("mma.sync.aligned.m16n8k16.row.col.f32.bf16.bf16.f32 " \
        "{%0,%1,%2,%3}, {%4,%5,%6,%7}, {%8,%9}, {%0,%1,%2,%3};" \
        : "+f"((d)[0]), "+f"((d)[1]), "+f"((d)[2]), "+f"((d)[3]) \
        : "r"((a)[0]), "r"((a)[1]), "r"((a)[2]), "r"((a)[3]), "r"(b0), "r"(b1))

// Fill a 128x256 bf16 tile into padded-row smem (row stride RSTRIDE bytes).
__device__ __forceinline__ void fill_tile(unsigned sbase, const uint4* __restrict__ src,
                                          int t0, int stride) {
#pragma unroll 4
    for (int idx = t0; idx < 4096; idx += stride) {
        uint4 v = src[idx];
        STS128(v.x, v.y, v.z, v.w,
               sbase + (unsigned)(idx >> 5) * RSTRIDE + (unsigned)(idx & 31) * 16u);
    }
}

__global__ void __launch_bounds__(512) convert_bf16(const float* __restrict__ img,
                                                    const float* __restrict__ txt)
{
    unsigned t = blockIdx.x * 512u + threadIdx.x;
    const float* src = (t >> 20) ? txt : img;
    __nv_bfloat16* dst = g_bf[t >> 20];
    unsigned i = (t & 0xFFFFFu) << 2;
    float4 v = *(const float4*)(src + i);
    *(uint2*)(dst + i) = make_uint2(bf16x2_pack(v.x, v.y), bf16x2_pack(v.z, v.w));
}

// Persistent: 148 CTAs, static unit ranges. Unit = (rowblock rb = u>>3, chunk = u&7).
// Row stats carried across contiguous units of the same rowblock.
__global__ void __launch_bounds__(512, 1)
clip_main(const float* __restrict__ scale_ptr)
{
    extern __shared__ char dsm[];
    __shared__ __align__(8) unsigned long long sh_bar[4];
    __shared__ float sm_m[512], sm_s[512], sm_p[128];

    const int tid = threadIdx.x, wid = tid >> 5, lane = tid & 31;
    const int cta = blockIdx.x;
    const int u0 = (cta * NUNITS) / NCTA;
    const int u1 = ((cta + 1) * NUNITS) / NCTA;

    const unsigned abase = smem_u32(dsm);
    const unsigned bb[2] = { abase + TILE_B, abase + 2u * TILE_B };
    const unsigned smbar = smem_u32(sh_bar);

    if (tid == 0) {
        MBARRIER_INIT(smbar + 0, 256);  MBARRIER_INIT(smbar + 8, 256);
        MBARRIER_INIT(smbar + 16, 256); MBARRIER_INIT(smbar + 24, 256);
    }
    __syncthreads();

    const float scale = *scale_ptr;
    const float k2 = scale * 1.4426950408889634f;

    if (wid >= 8) {
        // ---------- Loaders: stream bf16 B tiles ----------
        const int ltid = tid - 256;
        const uint4* bsrc = (const uint4*)g_bf[1];
        int c = 0, ph[2] = {0, 0};
        for (int u = u0; u < u1; ++u) {
            const int chunk = u & 7;
            for (int t = 0; t < 16; ++t, ++c) {
                const int b = c & 1;
                if (c >= 2) { MBARRIER_WAIT(smbar + 16 + (b << 3), ph[b]); ph[b] ^= 1; }
                fill_tile(bb[b], bsrc + (size_t)(chunk * 16 + t) * 4096, ltid, 256);
                MBARRIER_ARRIVE(smbar + (b << 3));
            }
        }
    } else {
        // ---------- Compute warps ----------
        const int wx = wid & 1, wy = wid >> 1;
        unsigned aAddr[4];
#pragma unroll
        for (int mt = 0; mt < 4; ++mt) {
            unsigned row = (unsigned)(wx * 64 + mt * 16 + (lane & 7) + ((lane >> 3) & 1) * 8);
            aAddr[mt] = abase + row * RSTRIDE + (unsigned)(lane >> 4) * 16u;
        }
        unsigned bOff[2];
#pragma unroll
        for (int nt2 = 0; nt2 < 2; ++nt2) {
            unsigned row = (unsigned)(wy * 32 + nt2 * 16 + (lane & 7) + ((lane >> 4) & 1) * 8);
            bOff[nt2] = row * RSTRIDE + (unsigned)((lane >> 3) & 1) * 16u;
        }

        float mst[8], sst[8];
#pragma unroll
        for (int i = 0; i < 8; ++i) { mst[i] = -1e30f; sst[i] = 0.0f; }

        int c = 0, ph[2] = {0, 0}, prev_rb = -1, run_u0 = u0;

        for (int u = u0; u < u1; ++u) {
            const int rb = u >> 3, chunk = u & 7;
            const int rowBase = rb << 7;
            if (rb != prev_rb) {
                if (prev_rb >= 0) {
                    // ---- finalize run [run_u0, u) of prev_rb ----
                    if ((lane & 3) == 0) {
#pragma unroll
                        for (int mt = 0; mt < 4; ++mt)
#pragma unroll
                            for (int h = 0; h < 2; ++h) {
                                const int row = wx * 64 + mt * 16 + (lane >> 2) + 8 * h;
                                sm_m[wy * 128 + row] = mst[mt * 2 + h];
                                sm_s[wy * 128 + row] = sst[mt * 2 + h];
                            }
                    }
                    BAR_SYNC(1, 256);
                    if (tid < 128) {
                        float mM = sm_m[tid];
#pragma unroll
                        for (int q = 1; q < 4; ++q) mM = fmaxf(mM, sm_m[q * 128 + tid]);
                        float sM = 0.0f;
#pragma unroll
                        for (int q = 0; q < 4; ++q)
                            sM += sm_s[q * 128 + tid] * ex2f(k2 * (sm_m[q * 128 + tid] - mM));
                        g_rpu[(size_t)(u - 1) * 128 + tid] = make_float2(mM, sM);
                        const float2 neutral = make_float2(-1e30f, 0.0f);
                        for (int uu = run_u0; uu < u - 1; ++uu)
                            g_rpu[(size_t)uu * 128 + tid] = neutral;
                        const int dchunk = prev_rb >> 4;
                        const int clo = run_u0 - (prev_rb << 3), chi = u - (prev_rb << 3);
                        if (dchunk >= clo && dchunk < chi)
                            g_diag[(prev_rb << 7) + tid] = sm_p[tid];
                    }
                    BAR_SYNC(1, 256);
#pragma unroll
                    for (int i = 0; i < 8; ++i) { mst[i] = -1e30f; sst[i] = 0.0f; }
                    run_u0 = u;
                }
                fill_tile(abase, (const uint4*)(g_bf[0] + (size_t)rowBase * DIMK), tid, 256);
                BAR_SYNC(1, 256);
                prev_rb = rb;
            }

            for (int t = 0; t < 16; ++t, ++c) {
                const int b = c & 1;
                const int jj = chunk * 16 + t;
                MBARRIER_WAIT(smbar + (b << 3), ph[b]); ph[b] ^= 1;
                const unsigned bbase = bb[b];

                float acc[4][4][4];
#pragma unroll
                for (int mt = 0; mt < 4; ++mt)
#pragma unroll
                    for (int nt = 0; nt < 4; ++nt)
#pragma unroll
                        for (int e = 0; e < 4; ++e) acc[mt][nt][e] = 0.0f;

#pragma unroll 4
                for (int ks = 0; ks < 16; ++ks) {
                    const unsigned ko = (unsigned)ks * 32u;
                    unsigned a[4][4];
#pragma unroll
                    for (int mt = 0; mt < 4; ++mt) LDSM_X4(a[mt], aAddr[mt] + ko);
#pragma unroll
                    for (int nt2 = 0; nt2 < 2; ++nt2) {
                        unsigned bf[4];
                        LDSM_X4T(bf, bbase + bOff[nt2] + ko);
#pragma unroll
                        for (int mt = 0; mt < 4; ++mt) {
                            MMA16816(acc[mt][nt2 * 2 + 0], a[mt], bf[0], bf[1]);
                            MMA16816(acc[mt][nt2 * 2 + 1], a[mt], bf[2], bf[3]);
                        }
                    }
                }
                MBARRIER_ARRIVE(smbar + 16 + (b << 3));

                // Row-direction online LSE (warp-uniform skip; stats carried across units)
#pragma unroll
                for (int mt = 0; mt < 4; ++mt)
#pragma unroll
                    for (int h = 0; h < 2; ++h) {
                        const int st = mt * 2 + h;
                        float v[8];
#pragma unroll
                        for (int nt = 0; nt < 4; ++nt) {
                            v[nt * 2 + 0] = acc[mt][nt][h * 2 + 0];
                            v[nt * 2 + 1] = acc[mt][nt][h * 2 + 1];
                        }
                        if (jj == rb) {
                            const int row = wx * 64 + mt * 16 + (lane >> 2) + 8 * h;
#pragma unroll
                            for (int nt = 0; nt < 4; ++nt)
#pragma unroll
                                for (int e = 0; e < 2; ++e) {
                                    const int col = wy * 32 + nt * 8 + 2 * (lane & 3) + e;
                                    if (col == row) sm_p[row] = v[nt * 2 + e];
                                }
                        }
                        float vm = v[0];
#pragma unroll
                        for (int i = 1; i < 8; ++i) vm = fmaxf(vm, v[i]);
                        vm = fmaxf(vm, __shfl_xor_sync(0xffffffffu, vm, 1));
                        vm = fmaxf(vm, __shfl_xor_sync(0xffffffffu, vm, 2));
                        if (__all_sync(0xffffffffu, vm < mst[st] - 2.0f)) continue;
                        const float mnew = fmaxf(mst[st], vm);
                        const float base = k2 * mnew;
                        float sum = expsum8_m(v, k2, base);
                        sum += __shfl_xor_sync(0xffffffffu, sum, 1);
                        sum += __shfl_xor_sync(0xffffffffu, sum, 2);
                        sst[st] = fmaf(sst[st], ex2f(fmaf(mst[st], k2, -base)), sum);
                        mst[st] = mnew;
                    }

                // Column partial over this warp's 64 rows
                {
                    float cm[8], cs[8];
#pragma unroll
                    for (int nt = 0; nt < 4; ++nt)
#pragma unroll
                        for (int e = 0; e < 2; ++e) {
                            const int ci = nt * 2 + e;
                            float v0 = fmaxf(fmaxf(acc[0][nt][e], acc[0][nt][2 + e]),
                                             fmaxf(acc[1][nt][e], acc[1][nt][2 + e]));
                            float v1 = fmaxf(fmaxf(acc[2][nt][e], acc[2][nt][2 + e]),
                                             fmaxf(acc[3][nt][e], acc[3][nt][2 + e]));
                            cm[ci] = fmaxf(v0, v1);
                        }
#pragma unroll
                    for (int ci = 0; ci < 8; ++ci) {
                        cm[ci] = fmaxf(cm[ci], __shfl_xor_sync(0xffffffffu, cm[ci], 4));
                        cm[ci] = fmaxf(cm[ci], __shfl_xor_sync(0xffffffffu, cm[ci], 8));
                        cm[ci] = fmaxf(cm[ci], __shfl_xor_sync(0xffffffffu, cm[ci], 16));
                    }
#pragma unroll
                    for (int nt = 0; nt < 4; ++nt)
#pragma unroll
                        for (int e = 0; e < 2; ++e) {
                            const int ci = nt * 2 + e;
                            float v[8];
#pragma unroll
                            for (int mt = 0; mt < 4; ++mt) {
                                v[mt * 2 + 0] = acc[mt][nt][e];
                                v[mt * 2 + 1] = acc[mt][nt][2 + e];
                            }
                            cs[ci] = expsum8_m(v, k2, k2 * cm[ci]);
                        }
#pragma unroll
                    for (int ci = 0; ci < 8; ++ci) {
                        cs[ci] += __shfl_xor_sync(0xffffffffu, cs[ci], 4);
                        cs[ci] += __shfl_xor_sync(0xffffffffu, cs[ci], 8);
                        cs[ci] += __shfl_xor_sync(0xffffffffu, cs[ci], 16);
                    }
                    if (lane < 4) {
#pragma unroll
                        for (int nt = 0; nt < 4; ++nt)
#pragma unroll
                            for (int e = 0; e < 2; ++e) {
                                const int ci = nt * 2 + e;
                                const int cg = jj * 128 + wy * 32 + nt * 8 + 2 * lane + e;
                                g_cp[(size_t)(rb * 2 + wx) * N_TOK + cg] = make_float2(cm[ci], cs[ci]);
                            }
                    }
                }
            }
        }

        // ---- finalize last run [run_u0, u1) ----
        if ((lane & 3) == 0) {
#pragma unroll
            for (int mt = 0; mt < 4; ++mt)
#pragma unroll
                for (int h = 0; h < 2; ++h) {
                    const int row = wx * 64 + mt * 16 + (lane >> 2) + 8 * h;
                    sm_m[wy * 128 + row] = mst[mt * 2 + h];
                    sm_s[wy * 128 + row] = sst[mt * 2 + h];
                }
        }
        BAR_SYNC(1, 256);
        if (tid < 128) {
            float mM = sm_m[tid];
#pragma unroll
            for (int q = 1; q < 4; ++q) mM = fmaxf(mM, sm_m[q * 128 + tid]);
            float sM = 0.0f;
#pragma unroll
            for (int q = 0; q < 4; ++q)
                sM += sm_s[q * 128 + tid] * ex2f(k2 * (sm_m[q * 128 + tid] - mM));
            g_rpu[(size_t)(u1 - 1) * 128 + tid] = make_float2(mM, sM);
            const float2 neutral = make_float2(-1e30f, 0.0f);
            for (int uu = run_u0; uu < u1 - 1; ++uu)
                g_rpu[(size_t)uu * 128 + tid] = neutral;
            const int dchunk = prev_rb >> 4;
            const int clo = run_u0 - (prev_rb << 3), chi = u1 - (prev_rb << 3);
            if (dchunk >= clo && dchunk < chi)
                g_diag[(prev_rb << 7) + tid] = sm_p[tid];
        }
        BAR_SYNC(1, 256);
    }
}

__global__ void __launch_bounds__(256) clip_colred(const float* __restrict__ scale_ptr)
{
    const float scale = *scale_ptr;
    const float k2 = scale * 1.4426950408889634f;
    const int c = blockIdx.x * 256 + threadIdx.x;

    float M = -CUDART_INF_F;
#pragma unroll 4
    for (int i = 0; i < 256; ++i) M = fmaxf(M, g_cp[(size_t)i * N_TOK + c].x);
    float S = 0.0f;
#pragma unroll 4
    for (int i = 0; i < 256; ++i) {
        float2 p = g_cp[(size_t)i * N_TOK + c];
        S += p.y * ex2f(k2 * (p.x - M));
    }
    const float d = scale * g_diag[c];
    g_rowloss[N_TOK + c] = 0.69314718055994531f * fmaf(k2, M, __log2f(S)) - d;

    const int rb = c >> 7, lr = c & 127;
    float mM = -CUDART_INF_F;
#pragma unroll
    for (int k = 0; k < 8; ++k) mM = fmaxf(mM, g_rpu[(size_t)(rb * 8 + k) * 128 + lr].x);
    float sM = 0.0f;
#pragma unroll
    for (int k = 0; k < 8; ++k) {
        float2 p = g_rpu[(size_t)(rb * 8 + k) * 128 + lr];
        sM += p.y * ex2f(k2 * (p.x - mM));
    }
    g_rowloss[c] = 0.69314718055994531f * fmaf(k2, mM, __log2f(sM)) - d;
}

__global__ void __launch_bounds__(1024) clip_reduce(float* __restrict__ out)
{
    __shared__ float sm[1024];
    float a = 0.0f;
    const float4* p = (const float4*)g_rowloss;
#pragma unroll 4
    for (int i = threadIdx.x; i < 8192; i += 1024) {
        float4 v = p[i];
        a += (v.x + v.y) + (v.z + v.w);
    }
    sm[threadIdx.x] = a;
    __syncthreads();
    for (int st = 512; st > 0; st >>= 1) {
        if (threadIdx.x < st) sm[threadIdx.x] += sm[threadIdx.x + st];
        __syncthreads();
    }
    if (threadIdx.x == 0) out[0] = sm[0] * (1.0f / 32768.0f);
}

extern "C" void kernel_launch(void* const* d_in, const int* in_sizes, int n_in,
                              void* d_out, int out_size)
{
    (void)in_sizes; (void)n_in; (void)out_size;
    const float* img = (const float*)d_in[0];
    const float* txt = (const float*)d_in[1];
    const float* scl = (const float*)d_in[2];

    cudaFuncSetAttribute(clip_main, cudaFuncAttributeMaxDynamicSharedMemorySize, SMEM_DYN);
    convert_bf16<<<4096, 512>>>(img, txt);
    clip_main<<<NCTA, 512, SMEM_DYN>>>(scl);
    clip_colred<<<64, 256>>>(scl);
    clip_reduce<<<1, 1024>>>((float*)d_out);
}